// round 7
// baseline (speedup 1.0000x reference)
#include <cuda_runtime.h>
#include <cuda_fp16.h>
#include <cstdint>

#define NN 100000
#define DF 64
#define NE 1600000
#define NB ((NN + 1023) / 1024)   // 98 scan blocks

static constexpr float DTC     = 0.2f;
static constexpr float HALF_DT = 0.1f;
static constexpr float DT6     = 0.2f / 6.0f;

// ---------------- scratch (static device globals) ----------------
__device__ int     g_deg1[NN];          // masked row degree (hop-1 CSR)
__device__ int     g_deg2[NN];          // full row degree   (hop-2 CSR)
__device__ int     g_deg_c[NN];         // full col degree
__device__ int     g_cur1[NN];
__device__ int     g_cur2[NN];
__device__ float   g_dinv_r[NN];        // row factor (applied to warp sum)
__device__ float   g_premul[NN];        // mask * dinv_c (folded into u)
__device__ float   g_dd[NN];            // dinv_r * dinv_c (folded into t1)
__device__ int     g_rp1[NN + 1];
__device__ int     g_rp2[NN + 1];
__device__ int     g_part[NB];
__device__ int     g_ecol1[NE];         // masked CSR cols (~half used)
__device__ int     g_ecol2[NE];         // full CSR cols
__device__ __half2 g_uh [NN * DF / 2];  // stage input * mask*dinv_c, fp16
__device__ __half2 g_t1h[NN * DF / 2];  // hop-1 out * dinv_r*dinv_c, fp16
__device__ float4  g_acc[NN * DF / 4];  // k1 + 2k2 + 2k3

// ---------------- preprocessing ----------------
__global__ void zero_kernel() {
    int i = blockIdx.x * blockDim.x + threadIdx.x;
    if (i < NN) { g_deg1[i] = 0; g_deg2[i] = 0; g_deg_c[i] = 0;
                  g_cur1[i] = 0; g_cur2[i] = 0; }
}

__global__ void hist_kernel(const int* __restrict__ row, const int* __restrict__ col,
                            const int* __restrict__ mask) {
    int e = blockIdx.x * blockDim.x + threadIdx.x;
    if (e < NE) {
        int r = row[e], c = col[e];
        atomicAdd(&g_deg2[r], 1);
        atomicAdd(&g_deg_c[c], 1);
        if (mask[c]) atomicAdd(&g_deg1[r], 1);
    }
}

__global__ void dinv_kernel(const int* __restrict__ mask) {
    int i = blockIdx.x * blockDim.x + threadIdx.x;
    if (i < NN) {
        int dr = g_deg2[i];
        int dc = g_deg_c[i];
        float ir = dr > 0 ? rsqrtf((float)dr) : 0.0f;
        float ic = dc > 0 ? rsqrtf((float)dc) : 0.0f;
        g_dinv_r[i] = ir;
        g_premul[i] = mask[i] ? ic : 0.0f;
        g_dd[i]     = ir * ic;
    }
}

// Two-level scan (P selects CSR 1 or 2; globals resolved in DEVICE code only)
template <int P>
__global__ void scan_block_kernel() {
    const int* __restrict__ deg = (P == 1) ? g_deg1 : g_deg2;
    int* __restrict__ rp        = (P == 1) ? g_rp1  : g_rp2;
    __shared__ int wsum[32];
    int b = blockIdx.x, t = threadIdx.x, lane = t & 31, wid = t >> 5;
    int i = b * 1024 + t;
    int v = (i < NN) ? deg[i] : 0;
    int incl = v;
    #pragma unroll
    for (int off = 1; off < 32; off <<= 1) {
        int x = __shfl_up_sync(0xffffffffu, incl, off);
        if (lane >= off) incl += x;
    }
    if (lane == 31) wsum[wid] = incl;
    __syncthreads();
    if (wid == 0) {
        int ws = wsum[lane];
        int wincl = ws;
        #pragma unroll
        for (int off = 1; off < 32; off <<= 1) {
            int x = __shfl_up_sync(0xffffffffu, wincl, off);
            if (lane >= off) wincl += x;
        }
        wsum[lane] = wincl - ws;
    }
    __syncthreads();
    int excl = incl - v + wsum[wid];
    if (i < NN) rp[i] = excl;
    if (t == 1023) g_part[b] = excl + v;
}

template <int P>
__global__ void scan_part_kernel() {
    int* __restrict__ rp = (P == 1) ? g_rp1 : g_rp2;
    if (threadIdx.x == 0) {
        int s = 0;
        for (int b = 0; b < NB; b++) { int v = g_part[b]; g_part[b] = s; s += v; }
        rp[NN] = s;
    }
}

template <int P>
__global__ void scan_add_kernel() {
    int* __restrict__ rp = (P == 1) ? g_rp1 : g_rp2;
    int i = blockIdx.x * 1024 + threadIdx.x;
    if (i < NN) rp[i] += g_part[blockIdx.x];
}

__global__ void scatter_kernel(const int* __restrict__ row, const int* __restrict__ col,
                               const int* __restrict__ mask) {
    int e = blockIdx.x * blockDim.x + threadIdx.x;
    if (e < NE) {
        int r = row[e], c = col[e];
        int p2 = g_rp2[r] + atomicAdd(&g_cur2[r], 1);
        g_ecol2[p2] = c;
        if (mask[c]) {
            int p1 = g_rp1[r] + atomicAdd(&g_cur1[r], 1);
            g_ecol1[p1] = c;
        }
    }
}

// uh = mask*dinv_c * r0  (fp16), one float2 per thread
__global__ void init_u_kernel(const float* __restrict__ r0) {
    int i = blockIdx.x * blockDim.x + threadIdx.x;   // float2 index
    if (i < NN * DF / 2) {
        int node = i >> 5;
        float p = g_premul[node];
        float2 r = ((const float2*)r0)[i];
        g_uh[i] = __floats2half2_rn(p * r.x, p * r.y);
    }
}

// ---------------- gather core: warp per row, 2 edges per iteration ----------------
// Lanes 0-15 handle even-indexed edge of a pair, 16-31 the odd one. Each lane
// loads a uint2 (features 4m..4m+3). Full 16-edge chunks have no validity checks.
#define RG_LOAD(t, dst) \
    { int cj = __shfl_sync(0xffffffffu, c, 2 * (t) + g); \
      dst = __ldg((const uint2*)(xb + (((size_t)cj) << 7) + moff)); }
#define RG_ACC(dst) \
    { float2 f0 = __half22float2(*(const __half2*)&dst.x); \
      float2 f1 = __half22float2(*(const __half2*)&dst.y); \
      a0 += f0.x; a1 += f0.y; a2 += f1.x; a3 += f1.y; }

template <int CSR>
__device__ __forceinline__ float4 row_gather(int wi, int lane) {
    const int* __restrict__ rp = (CSR == 0) ? g_rp1   : g_rp2;
    const int* __restrict__ ec = (CSR == 0) ? g_ecol1 : g_ecol2;
    const char* __restrict__ xb = (const char*)((CSR == 0) ? g_uh : g_t1h);

    int s = rp[wi];
    int e = rp[wi + 1];
    int g = lane >> 4;
    int m = lane & 15;
    unsigned moff = m << 3;

    float a0 = 0.f, a1 = 0.f, a2 = 0.f, a3 = 0.f;
    int nfull = (e - s) & ~15;
    int base = s;

    for (; base < s + nfull; base += 16) {
        int c = __ldg(&ec[base + m]);
        uint2 d0, d1, d2, d3, d4, d5, d6, d7;
        RG_LOAD(0, d0) RG_LOAD(1, d1) RG_LOAD(2, d2) RG_LOAD(3, d3)
        RG_LOAD(4, d4) RG_LOAD(5, d5) RG_LOAD(6, d6) RG_LOAD(7, d7)
        RG_ACC(d0) RG_ACC(d1) RG_ACC(d2) RG_ACC(d3)
        RG_ACC(d4) RG_ACC(d5) RG_ACC(d6) RG_ACC(d7)
    }
    if (base < e) {
        int rem = e - base;                       // 1..15
        int c = __ldg(&ec[base + min(m, rem - 1)]);
        #pragma unroll
        for (int t = 0; t < 8; t++) {
            int src = 2 * t + g;
            int cj = __shfl_sync(0xffffffffu, c, src);
            if (src < rem) {
                uint2 d = __ldg((const uint2*)(xb + (((size_t)cj) << 7) + moff));
                RG_ACC(d)
            }
        }
    }
    a0 += __shfl_xor_sync(0xffffffffu, a0, 16);
    a1 += __shfl_xor_sync(0xffffffffu, a1, 16);
    a2 += __shfl_xor_sync(0xffffffffu, a2, 16);
    a3 += __shfl_xor_sync(0xffffffffu, a3, 16);
    return make_float4(a0, a1, a2, a3);
}

// hop-1: t1h[i] = dd[i] * sum_{masked e} uh[col_e]  (masked CSR)
__global__ void __launch_bounds__(256)
hop1_kernel() {
    int wi = (blockIdx.x * blockDim.x + threadIdx.x) >> 5;
    if (wi >= NN) return;
    int lane = threadIdx.x & 31;
    float4 sum = row_gather<0>(wi, lane);
    if (lane < 16) {
        float sc = g_dd[wi];
        __half2 h0 = __floats2half2_rn(sc * sum.x, sc * sum.y);
        __half2 h1 = __floats2half2_rn(sc * sum.z, sc * sum.w);
        ((uint2*)g_t1h)[wi * 16 + lane] =
            make_uint2(*(const unsigned*)&h0, *(const unsigned*)&h1);
    }
}

// hop-2 + RK4 epilogue. v = -dinv_r[i] * sum_e t1h[col_e]  (full CSR)
template <int MODE>
__global__ void __launch_bounds__(256)
hop2_kernel(const float* __restrict__ rin, float* __restrict__ outparam) {
    int wi = (blockIdx.x * blockDim.x + threadIdx.x) >> 5;
    if (wi >= NN) return;
    int lane = threadIdx.x & 31;
    float4 sum = row_gather<1>(wi, lane);
    if (lane >= 16) return;

    float sr = g_dinv_r[wi];
    float v0 = -sr * sum.x, v1 = -sr * sum.y, v2 = -sr * sum.z, v3 = -sr * sum.w;

    int o = wi * 16 + lane;                     // float4 index
    float4 r4 = ((const float4*)rin)[o];
    float p = g_premul[wi];

    float u0, u1, u2, u3;
    if (MODE == 1) {
        g_acc[o] = make_float4(v0, v1, v2, v3);
        u0 = r4.x + HALF_DT * v0; u1 = r4.y + HALF_DT * v1;
        u2 = r4.z + HALF_DT * v2; u3 = r4.w + HALF_DT * v3;
    } else if (MODE == 2) {
        float4 a = g_acc[o];
        g_acc[o] = make_float4(a.x + 2.f * v0, a.y + 2.f * v1,
                               a.z + 2.f * v2, a.w + 2.f * v3);
        u0 = r4.x + HALF_DT * v0; u1 = r4.y + HALF_DT * v1;
        u2 = r4.z + HALF_DT * v2; u3 = r4.w + HALF_DT * v3;
    } else if (MODE == 3) {
        float4 a = g_acc[o];
        g_acc[o] = make_float4(a.x + 2.f * v0, a.y + 2.f * v1,
                               a.z + 2.f * v2, a.w + 2.f * v3);
        u0 = r4.x + DTC * v0; u1 = r4.y + DTC * v1;
        u2 = r4.z + DTC * v2; u3 = r4.w + DTC * v3;
    } else {  // MODE 4: rnext = r + dt/6*(acc + v); u = rnext
        float4 a = g_acc[o];
        u0 = r4.x + DT6 * (a.x + v0); u1 = r4.y + DT6 * (a.y + v1);
        u2 = r4.z + DT6 * (a.z + v2); u3 = r4.w + DT6 * (a.w + v3);
        ((float4*)outparam)[o] = make_float4(u0, u1, u2, u3);
    }
    __half2 h0 = __floats2half2_rn(p * u0, p * u1);
    __half2 h1 = __floats2half2_rn(p * u2, p * u3);
    ((uint2*)g_uh)[o] = make_uint2(*(const unsigned*)&h0, *(const unsigned*)&h1);
}

// ---------------- launch ----------------
extern "C" void kernel_launch(void* const* d_in, const int* in_sizes, int n_in,
                              void* d_out, int out_size) {
    const float* r0   = (const float*)d_in[0];
    const int*   eidx = (const int*)d_in[1];
    const int*   mask = (const int*)d_in[2];
    const int* row = eidx;
    const int* col = eidx + NE;
    float* out = (float*)d_out;

    // CSR + normalization build (no device-global symbols passed from host!)
    zero_kernel<<<(NN + 255) / 256, 256>>>();
    hist_kernel<<<(NE + 255) / 256, 256>>>(row, col, mask);
    dinv_kernel<<<(NN + 255) / 256, 256>>>(mask);
    scan_block_kernel<1><<<NB, 1024>>>();
    scan_part_kernel <1><<<1, 32>>>();
    scan_add_kernel  <1><<<NB, 1024>>>();
    scan_block_kernel<2><<<NB, 1024>>>();
    scan_part_kernel <2><<<1, 32>>>();
    scan_add_kernel  <2><<<NB, 1024>>>();
    scatter_kernel   <<<(NE + 255) / 256, 256>>>(row, col, mask);

    // slice 0 = r0; uh = premul * r0
    cudaMemcpyAsync(out, r0, (size_t)NN * DF * sizeof(float),
                    cudaMemcpyDeviceToDevice, 0);
    init_u_kernel<<<(NN * DF / 2 + 255) / 256, 256>>>(r0);

    const int blocks = (NN * 32 + 255) / 256;  // warp per row

    for (int step = 0; step < 5; step++) {
        const float* r = out + (size_t)step * NN * DF;
        float* rnext   = out + (size_t)(step + 1) * NN * DF;

        hop1_kernel   <<<blocks, 256>>>();
        hop2_kernel<1><<<blocks, 256>>>(r, nullptr);
        hop1_kernel   <<<blocks, 256>>>();
        hop2_kernel<2><<<blocks, 256>>>(r, nullptr);
        hop1_kernel   <<<blocks, 256>>>();
        hop2_kernel<3><<<blocks, 256>>>(r, nullptr);
        hop1_kernel   <<<blocks, 256>>>();
        hop2_kernel<4><<<blocks, 256>>>(r, rnext);
    }
}

// round 8
// speedup vs baseline: 1.3177x; 1.3177x over previous
#include <cuda_runtime.h>
#include <cuda_fp16.h>
#include <cstdint>

#define NN 100000
#define DF 64
#define NE 1600000
#define NB ((NN + 1023) / 1024)   // 98 scan blocks

static constexpr float DTC     = 0.2f;
static constexpr float HALF_DT = 0.1f;
static constexpr float DT6     = 0.2f / 6.0f;

// ---------------- scratch (static device globals) ----------------
__device__ int     g_deg1[NN];          // masked row degree (hop-1 CSR)
__device__ int     g_deg2[NN];          // full row degree   (hop-2 CSR)
__device__ int     g_deg_c[NN];         // full col degree
__device__ int     g_cur1[NN];
__device__ int     g_cur2[NN];
__device__ float   g_dinv_r[NN];        // row factor (applied to warp sum)
__device__ float   g_premul[NN];        // mask * dinv_c (folded into u)
__device__ float   g_dd[NN];            // dinv_r * dinv_c (folded into t1)
__device__ int     g_rp1[NN + 1];
__device__ int     g_rp2[NN + 1];
__device__ int     g_part[NB];
__device__ int     g_ecol1[NE];         // masked CSR cols (~half used)
__device__ int     g_ecol2[NE];         // full CSR cols
__device__ __half2 g_uh [NN * DF / 2];  // stage input * mask*dinv_c, fp16
__device__ __half2 g_t1h[NN * DF / 2];  // hop-1 out * dinv_r*dinv_c, fp16
__device__ float2  g_acc[NN * DF / 2];  // k1 + 2k2 + 2k3

// ---------------- preprocessing ----------------
__global__ void zero_kernel() {
    int i = blockIdx.x * blockDim.x + threadIdx.x;
    if (i < NN) { g_deg1[i] = 0; g_deg2[i] = 0; g_deg_c[i] = 0;
                  g_cur1[i] = 0; g_cur2[i] = 0; }
}

__global__ void hist_kernel(const int* __restrict__ row, const int* __restrict__ col,
                            const int* __restrict__ mask) {
    int e = blockIdx.x * blockDim.x + threadIdx.x;
    if (e < NE) {
        int r = row[e], c = col[e];
        atomicAdd(&g_deg2[r], 1);
        atomicAdd(&g_deg_c[c], 1);
        if (mask[c]) atomicAdd(&g_deg1[r], 1);
    }
}

__global__ void dinv_kernel(const int* __restrict__ mask) {
    int i = blockIdx.x * blockDim.x + threadIdx.x;
    if (i < NN) {
        int dr = g_deg2[i];
        int dc = g_deg_c[i];
        float ir = dr > 0 ? rsqrtf((float)dr) : 0.0f;
        float ic = dc > 0 ? rsqrtf((float)dc) : 0.0f;
        g_dinv_r[i] = ir;
        g_premul[i] = mask[i] ? ic : 0.0f;
        g_dd[i]     = ir * ic;
    }
}

// Two-level scan (P selects CSR 1 or 2; globals resolved in DEVICE code only)
template <int P>
__global__ void scan_block_kernel() {
    const int* __restrict__ deg = (P == 1) ? g_deg1 : g_deg2;
    int* __restrict__ rp        = (P == 1) ? g_rp1  : g_rp2;
    __shared__ int wsum[32];
    int b = blockIdx.x, t = threadIdx.x, lane = t & 31, wid = t >> 5;
    int i = b * 1024 + t;
    int v = (i < NN) ? deg[i] : 0;
    int incl = v;
    #pragma unroll
    for (int off = 1; off < 32; off <<= 1) {
        int x = __shfl_up_sync(0xffffffffu, incl, off);
        if (lane >= off) incl += x;
    }
    if (lane == 31) wsum[wid] = incl;
    __syncthreads();
    if (wid == 0) {
        int ws = wsum[lane];
        int wincl = ws;
        #pragma unroll
        for (int off = 1; off < 32; off <<= 1) {
            int x = __shfl_up_sync(0xffffffffu, wincl, off);
            if (lane >= off) wincl += x;
        }
        wsum[lane] = wincl - ws;
    }
    __syncthreads();
    int excl = incl - v + wsum[wid];
    if (i < NN) rp[i] = excl;
    if (t == 1023) g_part[b] = excl + v;
}

template <int P>
__global__ void scan_part_kernel() {
    int* __restrict__ rp = (P == 1) ? g_rp1 : g_rp2;
    if (threadIdx.x == 0) {
        int s = 0;
        for (int b = 0; b < NB; b++) { int v = g_part[b]; g_part[b] = s; s += v; }
        rp[NN] = s;
    }
}

template <int P>
__global__ void scan_add_kernel() {
    int* __restrict__ rp = (P == 1) ? g_rp1 : g_rp2;
    int i = blockIdx.x * 1024 + threadIdx.x;
    if (i < NN) rp[i] += g_part[blockIdx.x];
}

__global__ void scatter_kernel(const int* __restrict__ row, const int* __restrict__ col,
                               const int* __restrict__ mask) {
    int e = blockIdx.x * blockDim.x + threadIdx.x;
    if (e < NE) {
        int r = row[e], c = col[e];
        int p2 = g_rp2[r] + atomicAdd(&g_cur2[r], 1);
        g_ecol2[p2] = c;
        if (mask[c]) {
            int p1 = g_rp1[r] + atomicAdd(&g_cur1[r], 1);
            g_ecol1[p1] = c;
        }
    }
}

// uh = mask*dinv_c * r0  (fp16), one float2 per thread
__global__ void init_u_kernel(const float* __restrict__ r0) {
    int i = blockIdx.x * blockDim.x + threadIdx.x;   // float2 index
    if (i < NN * DF / 2) {
        int node = i >> 5;
        float p = g_premul[node];
        float2 r = ((const float2*)r0)[i];
        g_uh[i] = __floats2half2_rn(p * r.x, p * r.y);
    }
}

// ---------------- gather core: warp per row, group-of-8 batched loads ----------
// Per 32-edge chunk: one coalesced col load; consume in fully-unrolled groups
// of 8 (8 shfl + 8 independent LDG.32 batched before accumulation -> MLP~8),
// dynamic tail of <8. Explicit scalars only (no local arrays -> no spill).
__device__ __forceinline__ float2
row_gather(const __half2* __restrict__ x, const int* __restrict__ ec,
           int s, int e, int lane) {
    float a0 = 0.0f, a1 = 0.0f;
    for (int base = s; base < e; base += 32) {
        int idx = base + lane;
        int c = (idx < e) ? __ldg(&ec[idx]) : 0;
        int n = min(32, e - base);
        int j = 0;
        for (; j + 8 <= n; j += 8) {
            int c0 = __shfl_sync(0xffffffffu, c, j + 0);
            int c1 = __shfl_sync(0xffffffffu, c, j + 1);
            int c2 = __shfl_sync(0xffffffffu, c, j + 2);
            int c3 = __shfl_sync(0xffffffffu, c, j + 3);
            int c4 = __shfl_sync(0xffffffffu, c, j + 4);
            int c5 = __shfl_sync(0xffffffffu, c, j + 5);
            int c6 = __shfl_sync(0xffffffffu, c, j + 6);
            int c7 = __shfl_sync(0xffffffffu, c, j + 7);
            __half2 v0 = __ldg(&x[c0 * (DF / 2) + lane]);
            __half2 v1 = __ldg(&x[c1 * (DF / 2) + lane]);
            __half2 v2 = __ldg(&x[c2 * (DF / 2) + lane]);
            __half2 v3 = __ldg(&x[c3 * (DF / 2) + lane]);
            __half2 v4 = __ldg(&x[c4 * (DF / 2) + lane]);
            __half2 v5 = __ldg(&x[c5 * (DF / 2) + lane]);
            __half2 v6 = __ldg(&x[c6 * (DF / 2) + lane]);
            __half2 v7 = __ldg(&x[c7 * (DF / 2) + lane]);
            float2 f0 = __half22float2(v0); a0 += f0.x; a1 += f0.y;
            float2 f1 = __half22float2(v1); a0 += f1.x; a1 += f1.y;
            float2 f2 = __half22float2(v2); a0 += f2.x; a1 += f2.y;
            float2 f3 = __half22float2(v3); a0 += f3.x; a1 += f3.y;
            float2 f4 = __half22float2(v4); a0 += f4.x; a1 += f4.y;
            float2 f5 = __half22float2(v5); a0 += f5.x; a1 += f5.y;
            float2 f6 = __half22float2(v6); a0 += f6.x; a1 += f6.y;
            float2 f7 = __half22float2(v7); a0 += f7.x; a1 += f7.y;
        }
        for (; j < n; j++) {
            int cj = __shfl_sync(0xffffffffu, c, j);
            float2 f = __half22float2(__ldg(&x[cj * (DF / 2) + lane]));
            a0 += f.x;
            a1 += f.y;
        }
    }
    return make_float2(a0, a1);
}

// hop-1: t1h[i] = dd[i] * sum_{masked e} uh[col_e]  (masked CSR)
__global__ void __launch_bounds__(256)
hop1_kernel() {
    int wi = (blockIdx.x * blockDim.x + threadIdx.x) >> 5;
    if (wi >= NN) return;
    int lane = threadIdx.x & 31;
    float2 sum = row_gather(g_uh, g_ecol1, g_rp1[wi], g_rp1[wi + 1], lane);
    float sc = g_dd[wi];
    g_t1h[wi * (DF / 2) + lane] = __floats2half2_rn(sc * sum.x, sc * sum.y);
}

// hop-2 + RK4 epilogue. v = -dinv_r[i] * sum_e t1h[col_e]  (full CSR)
// MODE 1 (k1): acc  = v;  u = r + 0.5*dt*v
// MODE 2 (k2): acc += 2v; u = r + 0.5*dt*v
// MODE 3 (k3): acc += 2v; u = r +     dt*v
// MODE 4 (k4): rnext = r + dt/6*(acc + v); u = rnext
template <int MODE>
__global__ void __launch_bounds__(256)
hop2_kernel(const float* __restrict__ rin, float* __restrict__ outparam) {
    int wi = (blockIdx.x * blockDim.x + threadIdx.x) >> 5;
    if (wi >= NN) return;
    int lane = threadIdx.x & 31;
    float2 sum = row_gather(g_t1h, g_ecol2, g_rp2[wi], g_rp2[wi + 1], lane);
    float sr = g_dinv_r[wi];
    float v0 = -sr * sum.x;
    float v1 = -sr * sum.y;

    int o = wi * (DF / 2) + lane;
    float2 r2 = ((const float2*)rin)[o];
    float p = g_premul[wi];

    if (MODE == 1) {
        g_acc[o] = make_float2(v0, v1);
        float u0 = r2.x + HALF_DT * v0, u1 = r2.y + HALF_DT * v1;
        g_uh[o] = __floats2half2_rn(p * u0, p * u1);
    } else if (MODE == 2) {
        float2 a = g_acc[o];
        g_acc[o] = make_float2(a.x + 2.0f * v0, a.y + 2.0f * v1);
        float u0 = r2.x + HALF_DT * v0, u1 = r2.y + HALF_DT * v1;
        g_uh[o] = __floats2half2_rn(p * u0, p * u1);
    } else if (MODE == 3) {
        float2 a = g_acc[o];
        g_acc[o] = make_float2(a.x + 2.0f * v0, a.y + 2.0f * v1);
        float u0 = r2.x + DTC * v0, u1 = r2.y + DTC * v1;
        g_uh[o] = __floats2half2_rn(p * u0, p * u1);
    } else {  // MODE 4
        float2 a = g_acc[o];
        float rn0 = r2.x + DT6 * (a.x + v0);
        float rn1 = r2.y + DT6 * (a.y + v1);
        ((float2*)outparam)[o] = make_float2(rn0, rn1);
        g_uh[o] = __floats2half2_rn(p * rn0, p * rn1);  // next step's k1 input
    }
}

// ---------------- launch ----------------
extern "C" void kernel_launch(void* const* d_in, const int* in_sizes, int n_in,
                              void* d_out, int out_size) {
    const float* r0   = (const float*)d_in[0];
    const int*   eidx = (const int*)d_in[1];
    const int*   mask = (const int*)d_in[2];
    const int* row = eidx;
    const int* col = eidx + NE;
    float* out = (float*)d_out;

    // CSR + normalization build (no device-global symbols passed from host!)
    zero_kernel<<<(NN + 255) / 256, 256>>>();
    hist_kernel<<<(NE + 255) / 256, 256>>>(row, col, mask);
    dinv_kernel<<<(NN + 255) / 256, 256>>>(mask);
    scan_block_kernel<1><<<NB, 1024>>>();
    scan_part_kernel <1><<<1, 32>>>();
    scan_add_kernel  <1><<<NB, 1024>>>();
    scan_block_kernel<2><<<NB, 1024>>>();
    scan_part_kernel <2><<<1, 32>>>();
    scan_add_kernel  <2><<<NB, 1024>>>();
    scatter_kernel   <<<(NE + 255) / 256, 256>>>(row, col, mask);

    // slice 0 = r0; uh = premul * r0
    cudaMemcpyAsync(out, r0, (size_t)NN * DF * sizeof(float),
                    cudaMemcpyDeviceToDevice, 0);
    init_u_kernel<<<(NN * DF / 2 + 255) / 256, 256>>>(r0);

    const int blocks = (NN * 32 + 255) / 256;  // warp per row

    for (int step = 0; step < 5; step++) {
        const float* r = out + (size_t)step * NN * DF;
        float* rnext   = out + (size_t)(step + 1) * NN * DF;

        hop1_kernel   <<<blocks, 256>>>();
        hop2_kernel<1><<<blocks, 256>>>(r, nullptr);
        hop1_kernel   <<<blocks, 256>>>();
        hop2_kernel<2><<<blocks, 256>>>(r, nullptr);
        hop1_kernel   <<<blocks, 256>>>();
        hop2_kernel<3><<<blocks, 256>>>(r, nullptr);
        hop1_kernel   <<<blocks, 256>>>();
        hop2_kernel<4><<<blocks, 256>>>(r, rnext);
    }
}